// round 13
// baseline (speedup 1.0000x reference)
#include <cuda_runtime.h>
#include <cuda_fp16.h>
#include <math.h>
#include <stdint.h>

#define NROWS 32768
#define HD    512

// ---------------------------------------------------------------------------
// primitives (sm_80+ path; no 'a'-suffix features)
// ---------------------------------------------------------------------------
__device__ __forceinline__ uint32_t smem_to_u32(const void* p) {
    uint32_t a;
    asm("{ .reg .u64 t; cvta.to.shared.u64 t, %1; cvt.u32.u64 %0, t; }" : "=r"(a) : "l"(p));
    return a;
}
__device__ __forceinline__ float tanh_ap(float x) {
    float y;
    asm("tanh.approx.f32 %0, %1;" : "=f"(y) : "f"(x));
    return y;
}

#define LDMATRIX_X4(r0, r1, r2, r3, addr) \
    asm volatile("ldmatrix.sync.aligned.m8n8.x4.shared.b16 {%0,%1,%2,%3}, [%4];" \
                 : "=r"(r0), "=r"(r1), "=r"(r2), "=r"(r3) : "r"(addr))
#define MMA16816(c, a, b) \
    asm volatile("mma.sync.aligned.m16n8k16.row.col.f32.f16.f16.f32 " \
                 "{%0,%1,%2,%3}, {%4,%5,%6,%7}, {%8,%9}, {%0,%1,%2,%3};" \
                 : "+f"((c)[0]), "+f"((c)[1]), "+f"((c)[2]), "+f"((c)[3]) \
                 : "r"((a)[0]), "r"((a)[1]), "r"((a)[2]), "r"((a)[3]), \
                   "r"((b)[0]), "r"((b)[1]))
#define CP_ASYNC16(dst, src) \
    asm volatile("cp.async.cg.shared.global [%0], [%1], 16;" :: "r"(dst), "l"(src))
#define CP_COMMIT() asm volatile("cp.async.commit_group;" ::: "memory")
#define CP_WAIT0()  asm volatile("cp.async.wait_group 0;" ::: "memory")

// ---------------------------------------------------------------------------
// device scratch (no allocations allowed)
// ---------------------------------------------------------------------------
__device__ int g_cnt0, g_cnt1;
__device__ int g_idx0[NROWS], g_idx1[NROWS];
__device__ __align__(16) __half g_A1L[(size_t)NROWS * 1536];  // stage-1 A, left (compact fp16)
__device__ __align__(16) __half g_A1R[(size_t)NROWS * 1536];  // stage-1 A, right
__device__ __align__(16) __half g_A2L[(size_t)NROWS * 512];   // stage-2 A, left (= hL)
__device__ __align__(16) __half g_A2R[(size_t)NROWS * 1024];  // stage-2 A, right (= [hR|lft])
__device__ __align__(16) __half g_W1t[4][512 * 1536];         // l1h,l1g,r1h,r1g  [N][K] fp16
__device__ __align__(16) __half g_W2Lt[2][512 * 512];         // l2h,l2g
__device__ __align__(16) __half g_W2Rt[2][512 * 1024];        // r2h,r2g

// ---------------------------------------------------------------------------
__global__ void reset_kernel() { g_cnt0 = 0; g_cnt1 = 0; }

// classify: 128 blocks x 256 threads, warp-aggregated atomics + coalesced zero
__global__ void __launch_bounds__(256) classify_kernel(const int* __restrict__ group,
                                                       float* __restrict__ out,
                                                       int write_mask) {
    __shared__ int s_g[256];
    const int tid = threadIdx.x;
    const int row = blockIdx.x * 256 + tid;
    const int lane = tid & 31;
    const int g = group[row];
    s_g[tid] = g;
    if (write_mask)
        out[(size_t)NROWS * HD + row] = (g == 2) ? 1.0f : 0.0f;

    unsigned m0 = __ballot_sync(0xFFFFFFFFu, g == 0);
    unsigned m1 = __ballot_sync(0xFFFFFFFFu, g == 1);
    int base0 = 0, base1 = 0;
    if (lane == 0) {
        if (m0) base0 = atomicAdd(&g_cnt0, __popc(m0));
        if (m1) base1 = atomicAdd(&g_cnt1, __popc(m1));
    }
    base0 = __shfl_sync(0xFFFFFFFFu, base0, 0);
    base1 = __shfl_sync(0xFFFFFFFFu, base1, 0);
    unsigned below = (1u << lane) - 1u;
    if (g == 0) g_idx0[base0 + __popc(m0 & below)] = row;
    if (g == 1) g_idx1[base1 + __popc(m1 & below)] = row;

    __syncthreads();
    const int row_base = blockIdx.x * 256;
    for (int r = 0; r < 256; ++r) {
        if (s_g[r] == 2) {
            float2* o = (float2*)(out + (size_t)(row_base + r) * HD);
            o[tid] = make_float2(0.0f, 0.0f);
        }
    }
}

__device__ __forceinline__ uint4 cvt8(const float4* sp) {
    float4 f0 = sp[0], f1 = sp[1];
    __half2 h0 = __floats2half2_rn(f0.x, f0.y);
    __half2 h1 = __floats2half2_rn(f0.z, f0.w);
    __half2 h2 = __floats2half2_rn(f1.x, f1.y);
    __half2 h3 = __floats2half2_rn(f1.z, f1.w);
    uint4 v;
    v.x = *(uint32_t*)&h0; v.y = *(uint32_t*)&h1;
    v.z = *(uint32_t*)&h2; v.w = *(uint32_t*)&h3;
    return v;
}

// ---------------------------------------------------------------------------
// merged prep: gather/convert A buffers AND weight transpose in ONE launch.
// ---------------------------------------------------------------------------
__global__ void __launch_bounds__(256) prep_kernel(
    const float* __restrict__ nh, const float* __restrict__ ncx,
    const float* __restrict__ le, const float* __restrict__ lft,
    const float* __restrict__ W0, const float* __restrict__ W1,
    const float* __restrict__ W2, const float* __restrict__ W3,
    const float* __restrict__ W4, const float* __restrict__ W5,
    const float* __restrict__ W6, const float* __restrict__ W7)
{
    __shared__ float t[32][33];
    __shared__ int s_gr[8];
    const int bid = blockIdx.x;
    const int th = threadIdx.x;
    if (bid < 8192) {
        const int side = bid >> 12;
        const int i0 = (bid & 4095) * 8;
        const int cnt = side ? g_cnt1 : g_cnt0;
        if (i0 >= cnt) return;
        const int* __restrict__ idx = side ? g_idx1 : g_idx0;
        if (th < 8) s_gr[th] = (i0 + th < cnt) ? idx[i0 + th] : -1;
        __syncthreads();
        __half* dstA = (side ? g_A1R : g_A1L) + (size_t)i0 * 1536;
        #pragma unroll
        for (int j = 0; j < 6; ++j) {
            int l = th + j * 256;
            int r = l / 192, q = l % 192;
            int gr = s_gr[r];
            if (gr < 0) continue;
            int kk = q * 8;
            const float* src = (kk < 512) ? nh : (kk < 1024) ? ncx : le;
            *(uint4*)(dstA + (size_t)r * 1536 + kk) =
                cvt8((const float4*)(src + (size_t)gr * 512 + (kk & 511)));
        }
        if (side) {
            #pragma unroll
            for (int j = 0; j < 2; ++j) {
                int l = th + j * 256;
                int r = l >> 6, q = l & 63;
                int gr = s_gr[r];
                if (gr < 0) continue;
                int kk = q * 8;
                *(uint4*)(g_A2R + (size_t)(i0 + r) * 1024 + 512 + kk) =
                    cvt8((const float4*)(lft + (size_t)gr * 512 + kk));
            }
        }
        return;
    }
    // ---- weight transpose ----
    const int wb = bid - 8192;
    const int id = wb / 768;
    const int rem = wb % 768;
    const int K = (id < 4) ? 1536 : (id < 6) ? 512 : 1024;
    const int k0 = (rem / 16) * 32;
    if (k0 >= K) return;
    const int n0 = (rem % 16) * 32;
    const float* W;
    __half* Wt;
    switch (id) {
        case 0: W = W0; Wt = g_W1t[0];  break;
        case 1: W = W1; Wt = g_W1t[1];  break;
        case 2: W = W2; Wt = g_W1t[2];  break;
        case 3: W = W3; Wt = g_W1t[3];  break;
        case 4: W = W4; Wt = g_W2Lt[0]; break;
        case 5: W = W5; Wt = g_W2Lt[1]; break;
        case 6: W = W6; Wt = g_W2Rt[0]; break;
        default: W = W7; Wt = g_W2Rt[1]; break;
    }
    const int tx = th & 31, ty = th >> 5;
    #pragma unroll
    for (int i = 0; i < 32; i += 8)
        t[ty + i][tx] = W[(size_t)(k0 + ty + i) * 512 + n0 + tx];
    __syncthreads();
    #pragma unroll
    for (int i = 0; i < 32; i += 8)
        Wt[(size_t)(n0 + ty + i) * K + k0 + tx] = __float2half(t[tx][ty + i]);
}

// ---------------------------------------------------------------------------
// gated GEMM, cp.async 2-stage pipeline, BK=64, BN=128 per stream:
//   C = tanh(A@Wh + bh) * sigmoid(A@Wg + bg)
// 512 threads, 16 warps (4m x 4n), each 32m x 32n x 2 streams.
// STAGE 1: A = g_A1{L,R} (K=1536), fp16 out -> g_A2L / g_A2R[:,0:512] compact.
// STAGE 2: A = g_A2L (K=512) / g_A2R (K=1024); fp32 out scattered to d_out.
// ---------------------------------------------------------------------------
#define NST   2
#define BK    64
#define BN    128
#define LDK   72                    // padded row stride in halfs (144B)
#define ST_A  (128 * LDK)           // 9216 halfs
#define ST_B  (BN * LDK)            // 9216 halfs per stream
#define ST_TOT (ST_A + 2 * ST_B)    // 27648 halfs = 55296 B per stage
#define SMEM_BYTES (NST * ST_TOT * 2)   // 110592 B

template <int STAGE>
__global__ void __launch_bounds__(512, 1) gemm_cp(
    const float* __restrict__ bhL, const float* __restrict__ bgL,
    const float* __restrict__ bhR, const float* __restrict__ bgR,
    float* __restrict__ outp)
{
    extern __shared__ __half smem[];
    __shared__ int s_idx[128];

    const int tid  = threadIdx.x;
    const int lane = tid & 31;
    const int wid  = tid >> 5;
    const int side = blockIdx.z;

    const int cnt  = side ? g_cnt1 : g_cnt0;
    const int row0 = blockIdx.y * 128;
    if (row0 >= cnt) return;
    const int n0 = blockIdx.x * BN;

    const int K = (STAGE == 1) ? 1536 : (side ? 1024 : 512);
    const __half* __restrict__ A;
    const __half* __restrict__ Wh;
    const __half* __restrict__ Wg;
    if (STAGE == 1) {
        A  = side ? g_A1R : g_A1L;
        Wh = g_W1t[side * 2];
        Wg = g_W1t[side * 2 + 1];
    } else {
        A  = side ? g_A2R : g_A2L;
        Wh = side ? g_W2Rt[0] : g_W2Lt[0];
        Wg = side ? g_W2Rt[1] : g_W2Lt[1];
    }
    const float* __restrict__ bh = side ? bhR : bhL;
    const float* __restrict__ bg = side ? bgR : bgL;
    __half* __restrict__ hdst = side ? g_A2R : g_A2L;
    const int K2dst = side ? 1024 : 512;   // stage-1 output row stride

    if (STAGE == 2 && tid < 128) {
        int rc = row0 + tid;
        s_idx[tid] = (rc < cnt) ? (side ? g_idx1 : g_idx0)[rc] : 0;
    }

    const uint32_t sb = smem_to_u32(smem);

    // ---- cp.async issue for chunk c (BK=64: 8 x 16B lines per row) ---------
    // A: 128 rows x 8 lines = 1024; B: 128 rows x 8 x 2 streams = 2048.
    // 3072 lines / 512 threads = 6 per thread.
    auto issue = [&](int c) {
        const uint32_t base = (uint32_t)(c & 1) * ST_TOT;
        const int kb = c * BK;
        #pragma unroll
        for (int it = 0; it < 2; ++it) {
            int l = tid + it * 512;
            int r = l >> 3, q = l & 7;
            uint32_t dst = sb + 2u * (base + r * LDK + q * 8);
            CP_ASYNC16(dst, A + (size_t)(row0 + r) * K + kb + q * 8);
        }
        #pragma unroll
        for (int it = 0; it < 2; ++it) {
            int l = tid + it * 512;
            int r = l >> 3, q = l & 7;
            uint32_t dh = sb + 2u * (base + ST_A + r * LDK + q * 8);
            CP_ASYNC16(dh, Wh + (size_t)(n0 + r) * K + kb + q * 8);
            CP_ASYNC16(dh + 2u * ST_B, Wg + (size_t)(n0 + r) * K + kb + q * 8);
        }
    };

    // ---- fragment addressing ------------------------------------------------
    const int wm = wid & 3;           // m warp 0..3 (32 rows)
    const int wn = wid >> 2;          // n warp 0..3 (32 cols per stream)
    const int rowA = wm * 32 + (lane & 15);
    const int colA = (lane >> 4) * 8;
    const int rowB = wn * 32 + (lane & 7) + ((lane >> 4) << 3);
    const int colB = ((lane >> 3) & 1) * 8;

    float ah[2][4][4];
    float ag[2][4][4];
    #pragma unroll
    for (int i = 0; i < 2; i++)
        #pragma unroll
        for (int j = 0; j < 4; j++)
            #pragma unroll
            for (int q = 0; q < 4; q++) { ah[i][j][q] = 0.f; ag[i][j][q] = 0.f; }

    const int nch = K / BK;
    issue(0); CP_COMMIT();

    for (int c = 0; c < nch; ++c) {
        CP_WAIT0();
        __syncthreads();
        // issue chunk c+1 into the other buffer (consumed in iter c-1)
        if (c + 1 < nch) { issue(c + 1); }
        CP_COMMIT();

        const uint32_t base = (uint32_t)(c & 1) * ST_TOT;
        #pragma unroll
        for (int k16 = 0; k16 < 4; ++k16) {
            const int kk = k16 * 16;
            uint32_t a[2][4];
            #pragma unroll
            for (int mt = 0; mt < 2; ++mt) {
                uint32_t ad = sb + 2u * (base + (rowA + mt * 16) * LDK + kk + colA);
                LDMATRIX_X4(a[mt][0], a[mt][1], a[mt][2], a[mt][3], ad);
            }
            uint32_t bhf[4][2], bgf[4][2];
            #pragma unroll
            for (int p = 0; p < 2; ++p) {
                uint32_t oh = sb + 2u * (base + ST_A + (rowB + p * 16) * LDK + kk + colB);
                LDMATRIX_X4(bhf[2 * p][0], bhf[2 * p][1], bhf[2 * p + 1][0], bhf[2 * p + 1][1], oh);
                LDMATRIX_X4(bgf[2 * p][0], bgf[2 * p][1], bgf[2 * p + 1][0], bgf[2 * p + 1][1],
                            oh + 2u * ST_B);
            }
            #pragma unroll
            for (int mt = 0; mt < 2; ++mt)
                #pragma unroll
                for (int nt = 0; nt < 4; ++nt) {
                    MMA16816(ah[mt][nt], a[mt], bhf[nt]);
                    MMA16816(ag[mt][nt], a[mt], bgf[nt]);
                }
        }
    }

    // ---- epilogue: bias + tanh * sigmoid ------------------------------------
    const int r0l   = wm * 32 + (lane >> 2);
    const int cbase = wn * 32 + (lane & 3) * 2;

    float bhv[4][2], bgv[4][2];
    #pragma unroll
    for (int nt = 0; nt < 4; ++nt) {
        int ncol = n0 + cbase + nt * 8;
        bhv[nt][0] = bh[ncol]; bhv[nt][1] = bh[ncol + 1];
        bgv[nt][0] = bg[ncol]; bgv[nt][1] = bg[ncol + 1];
    }

    #pragma unroll
    for (int mt = 0; mt < 2; ++mt) {
        #pragma unroll
        for (int hf = 0; hf < 2; ++hf) {
            const int rloc = r0l + mt * 16 + hf * 8;
            const int rc = row0 + rloc;
            if (rc >= cnt) continue;
            #pragma unroll
            for (int nt = 0; nt < 4; ++nt) {
                const int ncol = n0 + cbase + nt * 8;
                float hv0 = ah[mt][nt][hf * 2 + 0] + bhv[nt][0];
                float hv1 = ah[mt][nt][hf * 2 + 1] + bhv[nt][1];
                float gv0 = ag[mt][nt][hf * 2 + 0] + bgv[nt][0];
                float gv1 = ag[mt][nt][hf * 2 + 1] + bgv[nt][1];
                float o0 = tanh_ap(hv0) * (0.5f * tanh_ap(0.5f * gv0) + 0.5f);
                float o1 = tanh_ap(hv1) * (0.5f * tanh_ap(0.5f * gv1) + 0.5f);
                if (STAGE == 1) {
                    *(__half2*)&hdst[(size_t)rc * K2dst + ncol] = __floats2half2_rn(o0, o1);
                } else {
                    *(float2*)&outp[(size_t)s_idx[rloc] * 512 + ncol] = make_float2(o0, o1);
                }
            }
        }
    }
}

// ---------------------------------------------------------------------------
extern "C" void kernel_launch(void* const* d_in, const int* in_sizes, int n_in,
                              void* d_out, int out_size) {
    const float* nh   = (const float*)d_in[0];
    const float* nc   = (const float*)d_in[1];
    const float* le   = (const float*)d_in[2];
    const float* lft  = (const float*)d_in[3];
    const int*   grp  = (const int*)  d_in[4];
    const float* Wl1h = (const float*)d_in[5];
    const float* bl1h = (const float*)d_in[6];
    const float* Wl1g = (const float*)d_in[7];
    const float* bl1g = (const float*)d_in[8];
    const float* Wl2h = (const float*)d_in[9];
    const float* bl2h = (const float*)d_in[10];
    const float* Wl2g = (const float*)d_in[11];
    const float* bl2g = (const float*)d_in[12];
    const float* Wr1h = (const float*)d_in[13];
    const float* br1h = (const float*)d_in[14];
    const float* Wr1g = (const float*)d_in[15];
    const float* br1g = (const float*)d_in[16];
    const float* Wr2h = (const float*)d_in[17];
    const float* br2h = (const float*)d_in[18];
    const float* Wr2g = (const float*)d_in[19];
    const float* br2g = (const float*)d_in[20];

    float* out = (float*)d_out;
    const int write_mask = (out_size >= NROWS * HD + NROWS) ? 1 : 0;

    cudaFuncSetAttribute(gemm_cp<1>, cudaFuncAttributeMaxDynamicSharedMemorySize, SMEM_BYTES);
    cudaFuncSetAttribute(gemm_cp<2>, cudaFuncAttributeMaxDynamicSharedMemorySize, SMEM_BYTES);

    reset_kernel<<<1, 1>>>();
    classify_kernel<<<NROWS / 256, 256>>>(grp, out, write_mask);
    prep_kernel<<<8192 + 6144, 256>>>(nh, nc, le, lft,
                                      Wl1h, Wl1g, Wr1h, Wr1g, Wl2h, Wl2g, Wr2h, Wr2g);

    dim3 grid(HD / BN, NROWS / 128, 2);
    gemm_cp<1><<<grid, 512, SMEM_BYTES>>>(bl1h, bl1g, br1h, br1g, nullptr);
    gemm_cp<2><<<grid, 512, SMEM_BYTES>>>(bl2h, bl2g, br2h, br2g, out);
}

// round 14
// speedup vs baseline: 1.0302x; 1.0302x over previous
#include <cuda_runtime.h>
#include <cuda_fp16.h>
#include <math.h>
#include <stdint.h>

#define NROWS 32768
#define HD    512

// ---------------------------------------------------------------------------
// primitives (sm_80+ path; no 'a'-suffix features)
// ---------------------------------------------------------------------------
__device__ __forceinline__ uint32_t smem_to_u32(const void* p) {
    uint32_t a;
    asm("{ .reg .u64 t; cvta.to.shared.u64 t, %1; cvt.u32.u64 %0, t; }" : "=r"(a) : "l"(p));
    return a;
}
__device__ __forceinline__ float tanh_ap(float x) {
    float y;
    asm("tanh.approx.f32 %0, %1;" : "=f"(y) : "f"(x));
    return y;
}

#define LDMATRIX_X4(r0, r1, r2, r3, addr) \
    asm volatile("ldmatrix.sync.aligned.m8n8.x4.shared.b16 {%0,%1,%2,%3}, [%4];" \
                 : "=r"(r0), "=r"(r1), "=r"(r2), "=r"(r3) : "r"(addr))
#define MMA16816(c, a, b) \
    asm volatile("mma.sync.aligned.m16n8k16.row.col.f32.f16.f16.f32 " \
                 "{%0,%1,%2,%3}, {%4,%5,%6,%7}, {%8,%9}, {%0,%1,%2,%3};" \
                 : "+f"((c)[0]), "+f"((c)[1]), "+f"((c)[2]), "+f"((c)[3]) \
                 : "r"((a)[0]), "r"((a)[1]), "r"((a)[2]), "r"((a)[3]), \
                   "r"((b)[0]), "r"((b)[1]))
#define CP_ASYNC16(dst, src) \
    asm volatile("cp.async.cg.shared.global [%0], [%1], 16;" :: "r"(dst), "l"(src))
#define CP_COMMIT() asm volatile("cp.async.commit_group;" ::: "memory")

// ---------------------------------------------------------------------------
// device scratch (no allocations allowed)
// ---------------------------------------------------------------------------
__device__ int g_cnt0, g_cnt1;
__device__ int g_idx0[NROWS], g_idx1[NROWS];
__device__ __align__(16) __half g_A1L[(size_t)NROWS * 1536];  // stage-1 A, left (compact fp16)
__device__ __align__(16) __half g_A1R[(size_t)NROWS * 1536];  // stage-1 A, right
__device__ __align__(16) __half g_A2L[(size_t)NROWS * 512];   // stage-2 A, left (= hL)
__device__ __align__(16) __half g_A2R[(size_t)NROWS * 1024];  // stage-2 A, right (= [hR|lft])
__device__ __align__(16) __half g_W1t[4][512 * 1536];         // l1h,l1g,r1h,r1g  [N][K] fp16
__device__ __align__(16) __half g_W2Lt[2][512 * 512];         // l2h,l2g
__device__ __align__(16) __half g_W2Rt[2][512 * 1024];        // r2h,r2g

// ---------------------------------------------------------------------------
__global__ void reset_kernel() { g_cnt0 = 0; g_cnt1 = 0; }

// classify: 128 blocks x 256 threads, warp-aggregated atomics + coalesced zero
__global__ void __launch_bounds__(256) classify_kernel(const int* __restrict__ group,
                                                       float* __restrict__ out,
                                                       int write_mask) {
    __shared__ int s_g[256];
    const int tid = threadIdx.x;
    const int row = blockIdx.x * 256 + tid;
    const int lane = tid & 31;
    const int g = group[row];
    s_g[tid] = g;
    if (write_mask)
        out[(size_t)NROWS * HD + row] = (g == 2) ? 1.0f : 0.0f;

    unsigned m0 = __ballot_sync(0xFFFFFFFFu, g == 0);
    unsigned m1 = __ballot_sync(0xFFFFFFFFu, g == 1);
    int base0 = 0, base1 = 0;
    if (lane == 0) {
        if (m0) base0 = atomicAdd(&g_cnt0, __popc(m0));
        if (m1) base1 = atomicAdd(&g_cnt1, __popc(m1));
    }
    base0 = __shfl_sync(0xFFFFFFFFu, base0, 0);
    base1 = __shfl_sync(0xFFFFFFFFu, base1, 0);
    unsigned below = (1u << lane) - 1u;
    if (g == 0) g_idx0[base0 + __popc(m0 & below)] = row;
    if (g == 1) g_idx1[base1 + __popc(m1 & below)] = row;

    __syncthreads();
    const int row_base = blockIdx.x * 256;
    for (int r = 0; r < 256; ++r) {
        if (s_g[r] == 2) {
            float2* o = (float2*)(out + (size_t)(row_base + r) * HD);
            o[tid] = make_float2(0.0f, 0.0f);
        }
    }
}

__device__ __forceinline__ uint4 cvt8(const float4* sp) {
    float4 f0 = sp[0], f1 = sp[1];
    __half2 h0 = __floats2half2_rn(f0.x, f0.y);
    __half2 h1 = __floats2half2_rn(f0.z, f0.w);
    __half2 h2 = __floats2half2_rn(f1.x, f1.y);
    __half2 h3 = __floats2half2_rn(f1.z, f1.w);
    uint4 v;
    v.x = *(uint32_t*)&h0; v.y = *(uint32_t*)&h1;
    v.z = *(uint32_t*)&h2; v.w = *(uint32_t*)&h3;
    return v;
}

// ---------------------------------------------------------------------------
// merged prep: gather/convert A buffers AND weight transpose in ONE launch.
// ---------------------------------------------------------------------------
__global__ void __launch_bounds__(256) prep_kernel(
    const float* __restrict__ nh, const float* __restrict__ ncx,
    const float* __restrict__ le, const float* __restrict__ lft,
    const float* __restrict__ W0, const float* __restrict__ W1,
    const float* __restrict__ W2, const float* __restrict__ W3,
    const float* __restrict__ W4, const float* __restrict__ W5,
    const float* __restrict__ W6, const float* __restrict__ W7)
{
    __shared__ float t[32][33];
    __shared__ int s_gr[8];
    const int bid = blockIdx.x;
    const int th = threadIdx.x;
    if (bid < 8192) {
        const int side = bid >> 12;
        const int i0 = (bid & 4095) * 8;
        const int cnt = side ? g_cnt1 : g_cnt0;
        if (i0 >= cnt) return;
        const int* __restrict__ idx = side ? g_idx1 : g_idx0;
        if (th < 8) s_gr[th] = (i0 + th < cnt) ? idx[i0 + th] : -1;
        __syncthreads();
        __half* dstA = (side ? g_A1R : g_A1L) + (size_t)i0 * 1536;
        #pragma unroll
        for (int j = 0; j < 6; ++j) {
            int l = th + j * 256;
            int r = l / 192, q = l % 192;
            int gr = s_gr[r];
            if (gr < 0) continue;
            int kk = q * 8;
            const float* src = (kk < 512) ? nh : (kk < 1024) ? ncx : le;
            *(uint4*)(dstA + (size_t)r * 1536 + kk) =
                cvt8((const float4*)(src + (size_t)gr * 512 + (kk & 511)));
        }
        if (side) {
            #pragma unroll
            for (int j = 0; j < 2; ++j) {
                int l = th + j * 256;
                int r = l >> 6, q = l & 63;
                int gr = s_gr[r];
                if (gr < 0) continue;
                int kk = q * 8;
                *(uint4*)(g_A2R + (size_t)(i0 + r) * 1024 + 512 + kk) =
                    cvt8((const float4*)(lft + (size_t)gr * 512 + kk));
            }
        }
        return;
    }
    // ---- weight transpose ----
    const int wb = bid - 8192;
    const int id = wb / 768;
    const int rem = wb % 768;
    const int K = (id < 4) ? 1536 : (id < 6) ? 512 : 1024;
    const int k0 = (rem / 16) * 32;
    if (k0 >= K) return;
    const int n0 = (rem % 16) * 32;
    const float* W;
    __half* Wt;
    switch (id) {
        case 0: W = W0; Wt = g_W1t[0];  break;
        case 1: W = W1; Wt = g_W1t[1];  break;
        case 2: W = W2; Wt = g_W1t[2];  break;
        case 3: W = W3; Wt = g_W1t[3];  break;
        case 4: W = W4; Wt = g_W2Lt[0]; break;
        case 5: W = W5; Wt = g_W2Lt[1]; break;
        case 6: W = W6; Wt = g_W2Rt[0]; break;
        default: W = W7; Wt = g_W2Rt[1]; break;
    }
    const int tx = th & 31, ty = th >> 5;
    #pragma unroll
    for (int i = 0; i < 32; i += 8)
        t[ty + i][tx] = W[(size_t)(k0 + ty + i) * 512 + n0 + tx];
    __syncthreads();
    #pragma unroll
    for (int i = 0; i < 32; i += 8)
        Wt[(size_t)(n0 + ty + i) * K + k0 + tx] = __float2half(t[tx][ty + i]);
}

// ---------------------------------------------------------------------------
// gated GEMM, cp.async NSTC-stage pipeline, BKC-wide chunks:
//   C = tanh(A@Wh + bh) * sigmoid(A@Wg + bg)
// BM=128, BN=64 per stream (h+g). 256 threads, 8 warps (4m x 2n),
// each warp 32m x 32n x 2 streams. 2 CTAs/SM.
// STAGE 1: A = g_A1{L,R} (K=1536), fp16 out -> g_A2L / g_A2R[:,0:512] compact.
// STAGE 2: A = g_A2L (K=512) / g_A2R (K=1024); fp32 out scattered to d_out.
// ---------------------------------------------------------------------------
template <int STAGE, int BKC, int NSTC>
__global__ void __launch_bounds__(256, 2) gemm_cp(
    const float* __restrict__ bhL, const float* __restrict__ bgL,
    const float* __restrict__ bhR, const float* __restrict__ bgR,
    float* __restrict__ outp)
{
    constexpr int LDKC  = BKC + 8;           // padded row stride (halfs)
    constexpr int ST_A  = 128 * LDKC;
    constexpr int ST_B  = 64 * LDKC;
    constexpr int ST_TOT = ST_A + 2 * ST_B;  // = 256*LDKC halfs per stage
    constexpr int LPR   = BKC / 8;           // 16B lines per row

    extern __shared__ __half smem[];
    __shared__ int s_idx[128];

    const int tid  = threadIdx.x;
    const int lane = tid & 31;
    const int wid  = tid >> 5;
    const int side = blockIdx.z;

    const int cnt  = side ? g_cnt1 : g_cnt0;
    const int row0 = blockIdx.y * 128;
    if (row0 >= cnt) return;
    const int n0 = blockIdx.x * 64;

    const int K = (STAGE == 1) ? 1536 : (side ? 1024 : 512);
    const __half* __restrict__ A;
    const __half* __restrict__ Wh;
    const __half* __restrict__ Wg;
    if (STAGE == 1) {
        A  = side ? g_A1R : g_A1L;
        Wh = g_W1t[side * 2];
        Wg = g_W1t[side * 2 + 1];
    } else {
        A  = side ? g_A2R : g_A2L;
        Wh = side ? g_W2Rt[0] : g_W2Lt[0];
        Wg = side ? g_W2Rt[1] : g_W2Lt[1];
    }
    const float* __restrict__ bh = side ? bhR : bhL;
    const float* __restrict__ bg = side ? bgR : bgL;
    __half* __restrict__ hdst = side ? g_A2R : g_A2L;
    const int K2dst = side ? 1024 : 512;   // stage-1 output row stride

    if (STAGE == 2 && tid < 128) {
        int rc = row0 + tid;
        s_idx[tid] = (rc < cnt) ? (side ? g_idx1 : g_idx0)[rc] : 0;
    }

    const uint32_t sb = smem_to_u32(smem);

    // ---- cp.async issue for chunk c ----------------------------------------
    auto issue = [&](int c) {
        const uint32_t base = (uint32_t)(c % NSTC) * ST_TOT;
        const int kb = c * BKC;
        // A: 128 rows x LPR lines; LPR/2 iterations of 256 threads
        #pragma unroll
        for (int it = 0; it < LPR / 2; ++it) {
            int l = tid + it * 256;
            int r = l / LPR, q = l % LPR;
            uint32_t dst = sb + 2u * (base + r * LDKC + q * 8);
            CP_ASYNC16(dst, A + (size_t)(row0 + r) * K + kb + q * 8);
        }
        // Bh / Bg: 64 rows x LPR lines each; LPR/4 iterations per stream
        #pragma unroll
        for (int it = 0; it < LPR / 4; ++it) {
            int l = tid + it * 256;
            int r = l / LPR, q = l % LPR;
            uint32_t dh = sb + 2u * (base + ST_A + r * LDKC + q * 8);
            CP_ASYNC16(dh, Wh + (size_t)(n0 + r) * K + kb + q * 8);
            CP_ASYNC16(dh + 2u * ST_B, Wg + (size_t)(n0 + r) * K + kb + q * 8);
        }
    };

    // ---- fragment addressing ------------------------------------------------
    const int wm = wid & 3;
    const int wn = wid >> 2;
    const int rowA = wm * 32 + (lane & 15);
    const int colA = (lane >> 4) * 8;
    const int rowB = wn * 32 + (lane & 7) + ((lane >> 4) << 3);
    const int colB = ((lane >> 3) & 1) * 8;

    float ah[2][4][4];
    float ag[2][4][4];
    #pragma unroll
    for (int i = 0; i < 2; i++)
        #pragma unroll
        for (int j = 0; j < 4; j++)
            #pragma unroll
            for (int q = 0; q < 4; q++) { ah[i][j][q] = 0.f; ag[i][j][q] = 0.f; }

    const int nch = K / BKC;
    #pragma unroll
    for (int s = 0; s < NSTC - 1; ++s) {
        issue(s);
        CP_COMMIT();
    }

    for (int c = 0; c < nch; ++c) {
        asm volatile("cp.async.wait_group %0;" :: "n"(NSTC - 2) : "memory");
        __syncthreads();
        // prefetch chunk c+NSTC-1: its buffer was consumed in iter c-1,
        // and the barrier above guarantees all warps are past it.
        if (c + NSTC - 1 < nch) { issue(c + NSTC - 1); }
        CP_COMMIT();

        const uint32_t base = (uint32_t)(c % NSTC) * ST_TOT;
        #pragma unroll
        for (int k16 = 0; k16 < BKC / 16; ++k16) {
            const int kk = k16 * 16;
            uint32_t a[2][4];
            #pragma unroll
            for (int mt = 0; mt < 2; ++mt) {
                uint32_t ad = sb + 2u * (base + (rowA + mt * 16) * LDKC + kk + colA);
                LDMATRIX_X4(a[mt][0], a[mt][1], a[mt][2], a[mt][3], ad);
            }
            uint32_t bhf[4][2], bgf[4][2];
            #pragma unroll
            for (int p = 0; p < 2; ++p) {
                uint32_t oh = sb + 2u * (base + ST_A + (rowB + p * 16) * LDKC + kk + colB);
                LDMATRIX_X4(bhf[2 * p][0], bhf[2 * p][1], bhf[2 * p + 1][0], bhf[2 * p + 1][1], oh);
                LDMATRIX_X4(bgf[2 * p][0], bgf[2 * p][1], bgf[2 * p + 1][0], bgf[2 * p + 1][1],
                            oh + 2u * ST_B);
            }
            #pragma unroll
            for (int mt = 0; mt < 2; ++mt)
                #pragma unroll
                for (int nt = 0; nt < 4; ++nt) {
                    MMA16816(ah[mt][nt], a[mt], bhf[nt]);
                    MMA16816(ag[mt][nt], a[mt], bgf[nt]);
                }
        }
    }

    // ---- epilogue: bias + tanh * sigmoid ------------------------------------
    const int r0l   = wm * 32 + (lane >> 2);
    const int cbase = wn * 32 + (lane & 3) * 2;

    float bhv[4][2], bgv[4][2];
    #pragma unroll
    for (int nt = 0; nt < 4; ++nt) {
        int ncol = n0 + cbase + nt * 8;
        bhv[nt][0] = bh[ncol]; bhv[nt][1] = bh[ncol + 1];
        bgv[nt][0] = bg[ncol]; bgv[nt][1] = bg[ncol + 1];
    }

    #pragma unroll
    for (int mt = 0; mt < 2; ++mt) {
        #pragma unroll
        for (int hf = 0; hf < 2; ++hf) {
            const int rloc = r0l + mt * 16 + hf * 8;
            const int rc = row0 + rloc;
            if (rc >= cnt) continue;
            #pragma unroll
            for (int nt = 0; nt < 4; ++nt) {
                const int ncol = n0 + cbase + nt * 8;
                float hv0 = ah[mt][nt][hf * 2 + 0] + bhv[nt][0];
                float hv1 = ah[mt][nt][hf * 2 + 1] + bhv[nt][1];
                float gv0 = ag[mt][nt][hf * 2 + 0] + bgv[nt][0];
                float gv1 = ag[mt][nt][hf * 2 + 1] + bgv[nt][1];
                float o0 = tanh_ap(hv0) * (0.5f * tanh_ap(0.5f * gv0) + 0.5f);
                float o1 = tanh_ap(hv1) * (0.5f * tanh_ap(0.5f * gv1) + 0.5f);
                if (STAGE == 1) {
                    *(__half2*)&hdst[(size_t)rc * K2dst + ncol] = __floats2half2_rn(o0, o1);
                } else {
                    *(float2*)&outp[(size_t)s_idx[rloc] * 512 + ncol] = make_float2(o0, o1);
                }
            }
        }
    }
}

// ---------------------------------------------------------------------------
extern "C" void kernel_launch(void* const* d_in, const int* in_sizes, int n_in,
                              void* d_out, int out_size) {
    const float* nh   = (const float*)d_in[0];
    const float* nc   = (const float*)d_in[1];
    const float* le   = (const float*)d_in[2];
    const float* lft  = (const float*)d_in[3];
    const int*   grp  = (const int*)  d_in[4];
    const float* Wl1h = (const float*)d_in[5];
    const float* bl1h = (const float*)d_in[6];
    const float* Wl1g = (const float*)d_in[7];
    const float* bl1g = (const float*)d_in[8];
    const float* Wl2h = (const float*)d_in[9];
    const float* bl2h = (const float*)d_in[10];
    const float* Wl2g = (const float*)d_in[11];
    const float* bl2g = (const float*)d_in[12];
    const float* Wr1h = (const float*)d_in[13];
    const float* br1h = (const float*)d_in[14];
    const float* Wr1g = (const float*)d_in[15];
    const float* br1g = (const float*)d_in[16];
    const float* Wr2h = (const float*)d_in[17];
    const float* br2h = (const float*)d_in[18];
    const float* Wr2g = (const float*)d_in[19];
    const float* br2g = (const float*)d_in[20];

    float* out = (float*)d_out;
    const int write_mask = (out_size >= NROWS * HD + NROWS) ? 1 : 0;

    // stage 1: BK=96, NST=2 -> smem = 2 * 256*104 * 2B = 106496 B
    // stage 2: BK=64, NST=3 -> smem = 3 * 256*72  * 2B = 110592 B
    const int smem1 = 2 * 256 * 104 * 2;
    const int smem2 = 3 * 256 * 72 * 2;
    cudaFuncSetAttribute((const void*)gemm_cp<1, 96, 2>,
                         cudaFuncAttributeMaxDynamicSharedMemorySize, smem1);
    cudaFuncSetAttribute((const void*)gemm_cp<2, 64, 3>,
                         cudaFuncAttributeMaxDynamicSharedMemorySize, smem2);

    reset_kernel<<<1, 1>>>();
    classify_kernel<<<NROWS / 256, 256>>>(grp, out, write_mask);
    prep_kernel<<<8192 + 6144, 256>>>(nh, nc, le, lft,
                                      Wl1h, Wl1g, Wr1h, Wr1g, Wl2h, Wl2g, Wr2h, Wr2g);

    dim3 grid(8, NROWS / 128, 2);
    gemm_cp<1, 96, 2><<<grid, 256, smem1>>>(bl1h, bl1g, br1h, br1g, nullptr);
    gemm_cp<2, 64, 3><<<grid, 256, smem2>>>(bl2h, bl2g, br2h, br2g, out);
}